// round 10
// baseline (speedup 1.0000x reference)
#include <cuda_runtime.h>
#include <math.h>
#include <stdint.h>

// ---------------------------------------------------------------------------
// Model_25975962206896: 4-qubit VQC, B=524288.
// Z = s† (W† M W) s with s = v⊗v⊗v⊗v rank-1 ⇒ Z collapses to a 15-term
// trigonometric polynomial in (f0, f1).
//   setup_kernel: 1 block / 192 threads, shuffle-propagated popcount bins.
//   eval_kernel : 2 elements/thread, 128-thread blocks, grid 2048 for
//                 occupancy (latency-bound kernel needs TLP, not ILP).
// ---------------------------------------------------------------------------

__device__ float g_cA[15];
__device__ float g_cB[15];

__device__ __forceinline__ float2 cmulf(float2 a, float2 b) {
    return make_float2(a.x * b.x - a.y * b.y, a.x * b.y + a.y * b.x);
}
__device__ __forceinline__ float2 caddf(float2 a, float2 b) {
    return make_float2(a.x + b.x, a.y + b.y);
}

// ---------------------------------------------------------------------------
// Setup kernel: 1 block, 192 threads (proven R6 version).
// ---------------------------------------------------------------------------
__global__ void setup_kernel(const float* __restrict__ wU,
                             const float* __restrict__ wR) {
    __shared__ float2 gates[6][4][2][2];
    __shared__ float  isc[6], iss[6];
    __shared__ float2 sS[16][5];

    const int tid = threadIdx.x;

    if (tid >= 160 && tid < 184) {
        int t = tid - 160;
        int l = t / 4, qb = t % 4;
        float a = wR[l * 12 + qb * 3 + 0];
        float b = wR[l * 12 + qb * 3 + 1];
        float c = wR[l * 12 + qb * 3 + 2];
        float sa, ca, sb, cb, sc3, cc3;
        __sincosf(0.5f * a, &sa, &ca);
        __sincosf(0.5f * b, &sb, &cb);
        __sincosf(0.5f * c, &sc3, &cc3);
        // g = RX(a) * RZ(b) * RX(c)
        float2 m1_00 = make_float2(ca, 0.f), m1_01 = make_float2(0.f, -sa);
        float2 m1_10 = make_float2(0.f, -sa), m1_11 = make_float2(ca, 0.f);
        float2 e0 = make_float2(cb, -sb), e1 = make_float2(cb, sb);
        float2 m3_00 = make_float2(cc3, 0.f), m3_01 = make_float2(0.f, -sc3);
        float2 m3_10 = make_float2(0.f, -sc3), m3_11 = make_float2(cc3, 0.f);
        float2 m23_00 = cmulf(e0, m3_00), m23_01 = cmulf(e0, m3_01);
        float2 m23_10 = cmulf(e1, m3_10), m23_11 = cmulf(e1, m3_11);
        gates[l][qb][0][0] = caddf(cmulf(m1_00, m23_00), cmulf(m1_01, m23_10));
        gates[l][qb][0][1] = caddf(cmulf(m1_00, m23_01), cmulf(m1_01, m23_11));
        gates[l][qb][1][0] = caddf(cmulf(m1_10, m23_00), cmulf(m1_11, m23_10));
        gates[l][qb][1][1] = caddf(cmulf(m1_10, m23_01), cmulf(m1_11, m23_11));
    } else if (tid >= 184 && tid < 190) {
        int l = tid - 184;
        float s, c;
        __sincosf(wU[l], &s, &c);
        isc[l] = c;
        iss[l] = s;
    }
    __syncthreads();

    if (tid < 160) {
        const int n = tid >> 5;
        const int lane = tid & 31;
        const int r = lane & 15;
        float2 z = make_float2((__popc(r) == n) ? 1.f : 0.f, 0.f);

        const int PAIRS[12] = {1, 2, 1, 3, 1, 2, 1, 3, 0, 3, 0, 2};
#pragma unroll
        for (int l = 0; l < 6; l++) {
            {
                int mp = 8 >> PAIRS[2 * l], mq = 8 >> PAIRS[2 * l + 1];
                float c = isc[l], s = iss[l];
                float ox = __shfl_xor_sync(0xFFFFFFFFu, z.x, mp | mq);
                float oy = __shfl_xor_sync(0xFFFFFFFFu, z.y, mp | mq);
                bool act = ((r & mp) != 0) != ((r & mq) != 0);
                if (act)
                    z = make_float2(fmaf(c, z.x, -s * oy), fmaf(c, z.y, s * ox));
            }
#pragma unroll
            for (int qb = 0; qb < 4; qb++) {
                int mask = 8 >> qb;
                float ox = __shfl_xor_sync(0xFFFFFFFFu, z.x, mask);
                float oy = __shfl_xor_sync(0xFFFFFFFFu, z.y, mask);
                bool hi = (r & mask) != 0;
                float2 ga = hi ? gates[l][qb][1][1] : gates[l][qb][0][0];
                float2 gb = hi ? gates[l][qb][1][0] : gates[l][qb][0][1];
                float2 nz;
                nz.x = ga.x * z.x - ga.y * z.y + gb.x * ox - gb.y * oy;
                nz.y = ga.x * z.y + ga.y * z.x + gb.x * oy + gb.y * ox;
                z = nz;
            }
        }
        if (lane < 16) sS[r][n] = z;
    }
    __syncthreads();

    if (tid < 15) {
        const int NA[15] = {0, 0, 0, 0, 0, 1, 1, 1, 1, 2, 2, 2, 3, 3, 4};
        const int NB[15] = {0, 1, 2, 3, 4, 1, 2, 3, 4, 2, 3, 4, 3, 4, 4};
        int na = NA[tid], nb = NB[tid];
        float gx = 0.f, gy = 0.f;
#pragma unroll
        for (int i = 0; i < 16; i++) {
            float m = (i < 8) ? 1.f : -1.f;   // qubit 0 = bit 3
            float2 a = sS[i][na], b = sS[i][nb];
            gx += m * (a.x * b.x + a.y * b.y);
            gy += m * (a.x * b.y - a.y * b.x);
        }
        if (na == nb) { g_cA[tid] = gx;       g_cB[tid] = 0.f; }
        else          { g_cA[tid] = 2.f * gx; g_cB[tid] = -2.f * gy; }
    }
}

// ---------------------------------------------------------------------------
// Per-element evaluation, grouped by power p (shallow dependency tree).
// ---------------------------------------------------------------------------
__device__ __forceinline__ float eval_one(float f0, float f1,
                                          const float* __restrict__ A,
                                          const float* __restrict__ B) {
    float s, c, s1, c1;
    __sincosf(0.5f * f1, &s, &c);
    __sincosf(f0, &s1, &c1);

    float c2 = fmaf(2.0f * c1, c1, -1.0f);
    float s2 = 2.0f * s1 * c1;
    float c3 = fmaf(c2, c1, -s2 * s1);
    float s3 = fmaf(s2, c1, c2 * s1);
    float c4 = fmaf(c3, c1, -s3 * s1);
    float s4 = fmaf(s3, c1, c3 * s1);

    float cc = c * c, ss = s * s;
    float c4p = cc * cc, s4p = ss * ss;
    float c3p = cc * c, s3p = ss * s;
    float w0 = c4p * c4p;
    float w1 = (c4p * c3p) * s;
    float w2 = (c4p * cc) * ss;
    float w3 = (c4p * c) * s3p;
    float w4 = c4p * s4p;
    float w5 = c3p * (s4p * s);
    float w6 = cc * (s4p * ss);
    float w7 = c * (s4p * s3p);
    float w8 = s4p * s4p;

    float T1  = fmaf(A[1],  c1, B[1]  * s1);
    float T6  = fmaf(A[6],  c1, B[6]  * s1);
    float T10 = fmaf(A[10], c1, B[10] * s1);
    float T13 = fmaf(A[13], c1, B[13] * s1);
    float T2  = fmaf(A[2],  c2, B[2]  * s2);
    float T7  = fmaf(A[7],  c2, B[7]  * s2);
    float T11 = fmaf(A[11], c2, B[11] * s2);
    float T3  = fmaf(A[3],  c3, B[3]  * s3);
    float T8  = fmaf(A[8],  c3, B[8]  * s3);
    float T4  = fmaf(A[4],  c4, B[4]  * s4);

    float G0 = A[0];
    float G1 = T1;
    float G2 = A[5] + T2;
    float G3 = T6 + T3;
    float G4 = A[9] + T7 + T4;
    float G5 = T10 + T8;
    float G6 = A[12] + T11;
    float G7 = T13;
    float G8 = A[14];

    float t0 = fmaf(w0, G0, w1 * G1);
    float t1 = fmaf(w2, G2, w3 * G3);
    float t2 = fmaf(w4, G4, w5 * G5);
    float t3 = fmaf(w6, G6, w7 * G7);
    float t4 = w8 * G8;
    return (t0 + t1) + (t2 + t3) + t4;
}

// ---------------------------------------------------------------------------
// Eval kernel: 2 batch elements per thread (one float4 in, one float2 out).
// 128-thread blocks -> grid 2048 -> ~10 blocks/SM resident (occupancy play).
// ---------------------------------------------------------------------------
__global__ __launch_bounds__(128) void eval_kernel(
    const float4* __restrict__ in, const float* __restrict__ scp,
    const float* __restrict__ bip, float2* __restrict__ out) {
    float A[15], B[15];
#pragma unroll
    for (int k = 0; k < 15; k++) {
        A[k] = __ldg(&g_cA[k]);
        B[k] = __ldg(&g_cB[k]);
    }
    const float scale = __ldg(scp);
    const float bias  = __ldg(bip);
    const float K = 0.011180339887f;  // sqrt(2/1000)/4

    int t = blockIdx.x * blockDim.x + threadIdx.x;
    float4 v = in[t];

    float Z0 = eval_one(v.x, v.y, A, B);
    float Z1 = eval_one(v.z, v.w, A, B);

    float2 r;
    r.x = fmaf(scale, fmaf(K, fmaf(Z0, Z0, -1.0f), Z0), bias);
    r.y = fmaf(scale, fmaf(K, fmaf(Z1, Z1, -1.0f), Z1), bias);
    out[t] = r;
}

// ---------------------------------------------------------------------------
extern "C" void kernel_launch(void* const* d_in, const int* in_sizes, int n_in,
                              void* d_out, int out_size) {
    const float* inputs = (const float*)d_in[0];  // [B,2] float32
    const float* wU     = (const float*)d_in[1];  // [6]
    const float* wR     = (const float*)d_in[2];  // [6,4,3]
    const float* sc     = (const float*)d_in[3];  // [] out_scale
    const float* bi     = (const float*)d_in[4];  // [] out_bias

    setup_kernel<<<1, 192>>>(wU, wR);

    int nthreads = out_size / 2;  // 2 elements per thread
    int blocks = (nthreads + 127) / 128;
    eval_kernel<<<blocks, 128>>>((const float4*)inputs, sc, bi,
                                 (float2*)d_out);
}

// round 12
// speedup vs baseline: 1.0126x; 1.0126x over previous
#include <cuda_runtime.h>
#include <math.h>
#include <stdint.h>

// ---------------------------------------------------------------------------
// Model_25975962206896: 4-qubit VQC, B=524288.
// Z = s† (W† M W) s with s = v⊗v⊗v⊗v rank-1 ⇒ Z collapses to a 15-term
// trigonometric polynomial in (f0, f1).
//   setup_kernel: 1 block / 192 threads, shuffle-propagated popcount bins.
//   eval_kernel : 4 elements/thread as TWO packed f32x2 chains (Blackwell
//                 mul/add/fma.rn.f32x2) — halves the polynomial instruction
//                 count, which is the measured bottleneck. Packed coefficient
//                 broadcasts hoisted out of the per-pair evaluation.
// ---------------------------------------------------------------------------

__device__ float g_cA[15];
__device__ float g_cB[15];

typedef unsigned long long u64;

#define PK2(d, lo, hi) \
    asm("mov.b64 %0, {%1, %2};" : "=l"(d) \
        : "r"(__float_as_uint(lo)), "r"(__float_as_uint(hi)))
#define MUL2(d, a, b) \
    asm("mul.rn.f32x2 %0, %1, %2;" : "=l"(d) : "l"(a), "l"(b))
#define ADD2(d, a, b) \
    asm("add.rn.f32x2 %0, %1, %2;" : "=l"(d) : "l"(a), "l"(b))
#define FMA2(d, a, b, c) \
    asm("fma.rn.f32x2 %0, %1, %2, %3;" : "=l"(d) : "l"(a), "l"(b), "l"(c))
#define UPK2(lo, hi, src) do { \
    unsigned int _ua, _ub; \
    asm("mov.b64 {%0, %1}, %2;" : "=r"(_ua), "=r"(_ub) : "l"(src)); \
    lo = __uint_as_float(_ua); hi = __uint_as_float(_ub); } while (0)

__device__ __forceinline__ float2 cmulf(float2 a, float2 b) {
    return make_float2(a.x * b.x - a.y * b.y, a.x * b.y + a.y * b.x);
}
__device__ __forceinline__ float2 caddf(float2 a, float2 b) {
    return make_float2(a.x + b.x, a.y + b.y);
}

// ---------------------------------------------------------------------------
// Setup kernel: 1 block, 192 threads (proven R6 version, unchanged).
// ---------------------------------------------------------------------------
__global__ void setup_kernel(const float* __restrict__ wU,
                             const float* __restrict__ wR) {
    __shared__ float2 gates[6][4][2][2];
    __shared__ float  isc[6], iss[6];
    __shared__ float2 sS[16][5];

    const int tid = threadIdx.x;

    if (tid >= 160 && tid < 184) {
        int t = tid - 160;
        int l = t / 4, qb = t % 4;
        float a = wR[l * 12 + qb * 3 + 0];
        float b = wR[l * 12 + qb * 3 + 1];
        float c = wR[l * 12 + qb * 3 + 2];
        float sa, ca, sb, cb, sc3, cc3;
        __sincosf(0.5f * a, &sa, &ca);
        __sincosf(0.5f * b, &sb, &cb);
        __sincosf(0.5f * c, &sc3, &cc3);
        // g = RX(a) * RZ(b) * RX(c)
        float2 m1_00 = make_float2(ca, 0.f), m1_01 = make_float2(0.f, -sa);
        float2 m1_10 = make_float2(0.f, -sa), m1_11 = make_float2(ca, 0.f);
        float2 e0 = make_float2(cb, -sb), e1 = make_float2(cb, sb);
        float2 m3_00 = make_float2(cc3, 0.f), m3_01 = make_float2(0.f, -sc3);
        float2 m3_10 = make_float2(0.f, -sc3), m3_11 = make_float2(cc3, 0.f);
        float2 m23_00 = cmulf(e0, m3_00), m23_01 = cmulf(e0, m3_01);
        float2 m23_10 = cmulf(e1, m3_10), m23_11 = cmulf(e1, m3_11);
        gates[l][qb][0][0] = caddf(cmulf(m1_00, m23_00), cmulf(m1_01, m23_10));
        gates[l][qb][0][1] = caddf(cmulf(m1_00, m23_01), cmulf(m1_01, m23_11));
        gates[l][qb][1][0] = caddf(cmulf(m1_10, m23_00), cmulf(m1_11, m23_10));
        gates[l][qb][1][1] = caddf(cmulf(m1_10, m23_01), cmulf(m1_11, m23_11));
    } else if (tid >= 184 && tid < 190) {
        int l = tid - 184;
        float s, c;
        __sincosf(wU[l], &s, &c);
        isc[l] = c;
        iss[l] = s;
    }
    __syncthreads();

    if (tid < 160) {
        const int n = tid >> 5;
        const int lane = tid & 31;
        const int r = lane & 15;
        float2 z = make_float2((__popc(r) == n) ? 1.f : 0.f, 0.f);

        const int PAIRS[12] = {1, 2, 1, 3, 1, 2, 1, 3, 0, 3, 0, 2};
#pragma unroll
        for (int l = 0; l < 6; l++) {
            {
                int mp = 8 >> PAIRS[2 * l], mq = 8 >> PAIRS[2 * l + 1];
                float c = isc[l], s = iss[l];
                float ox = __shfl_xor_sync(0xFFFFFFFFu, z.x, mp | mq);
                float oy = __shfl_xor_sync(0xFFFFFFFFu, z.y, mp | mq);
                bool act = ((r & mp) != 0) != ((r & mq) != 0);
                if (act)
                    z = make_float2(fmaf(c, z.x, -s * oy), fmaf(c, z.y, s * ox));
            }
#pragma unroll
            for (int qb = 0; qb < 4; qb++) {
                int mask = 8 >> qb;
                float ox = __shfl_xor_sync(0xFFFFFFFFu, z.x, mask);
                float oy = __shfl_xor_sync(0xFFFFFFFFu, z.y, mask);
                bool hi = (r & mask) != 0;
                float2 ga = hi ? gates[l][qb][1][1] : gates[l][qb][0][0];
                float2 gb = hi ? gates[l][qb][1][0] : gates[l][qb][0][1];
                float2 nz;
                nz.x = ga.x * z.x - ga.y * z.y + gb.x * ox - gb.y * oy;
                nz.y = ga.x * z.y + ga.y * z.x + gb.x * oy + gb.y * ox;
                z = nz;
            }
        }
        if (lane < 16) sS[r][n] = z;
    }
    __syncthreads();

    if (tid < 15) {
        const int NA[15] = {0, 0, 0, 0, 0, 1, 1, 1, 1, 2, 2, 2, 3, 3, 4};
        const int NB[15] = {0, 1, 2, 3, 4, 1, 2, 3, 4, 2, 3, 4, 3, 4, 4};
        int na = NA[tid], nb = NB[tid];
        float gx = 0.f, gy = 0.f;
#pragma unroll
        for (int i = 0; i < 16; i++) {
            float m = (i < 8) ? 1.f : -1.f;   // qubit 0 = bit 3
            float2 a = sS[i][na], b = sS[i][nb];
            gx += m * (a.x * b.x + a.y * b.y);
            gy += m * (a.x * b.y - a.y * b.x);
        }
        if (na == nb) { g_cA[tid] = gx;       g_cB[tid] = 0.f; }
        else          { g_cA[tid] = 2.f * gx; g_cB[tid] = -2.f * gy; }
    }
}

// ---------------------------------------------------------------------------
// Packed pair evaluation: elements (a = lo lane, b = hi lane).
// Ap/Bp: pre-broadcast packed coefficients {A[k],A[k]} / {B[k],B[k]}.
// ---------------------------------------------------------------------------
__device__ __forceinline__ u64 eval_pair(
    float c1a, float s1a, float ca, float sa,
    float c1b, float s1b, float cb, float sb,
    const u64* __restrict__ Ap, const u64* __restrict__ Bp, u64 M1) {

    u64 C1, S1, C, S;
    PK2(C1, c1a, c1b);
    PK2(S1, s1a, s1b);
    PK2(C, ca, cb);
    PK2(S, sa, sb);

    // Chebyshev for m=2..4
    u64 two_c1, c2, s2, nS1, c3, s3, c4, s4, tmp;
    ADD2(two_c1, C1, C1);
    FMA2(c2, two_c1, C1, M1);          // 2c1^2 - 1
    MUL2(s2, two_c1, S1);              // 2 s1 c1
    MUL2(nS1, S1, M1);                 // -s1
    MUL2(tmp, s2, nS1);  FMA2(c3, c2, C1, tmp);
    MUL2(tmp, c2, S1);   FMA2(s3, s2, C1, tmp);
    MUL2(tmp, s3, nS1);  FMA2(c4, c3, C1, tmp);
    MUL2(tmp, c3, S1);   FMA2(s4, s3, C1, tmp);

    // powers of c, s
    u64 cc, ss, c4p, s4p, c3p, s3p;
    MUL2(cc, C, C);
    MUL2(ss, S, S);
    MUL2(c4p, cc, cc);
    MUL2(s4p, ss, ss);
    MUL2(c3p, cc, C);
    MUL2(s3p, ss, S);

    u64 w0, w1, w2, w3, w4, w5, w6, w7, w8;
    MUL2(w0, c4p, c4p);
    MUL2(tmp, c4p, c3p); MUL2(w1, tmp, S);
    MUL2(tmp, c4p, cc);  MUL2(w2, tmp, ss);
    MUL2(tmp, c4p, C);   MUL2(w3, tmp, s3p);
    MUL2(w4, c4p, s4p);
    MUL2(tmp, s4p, S);   MUL2(w5, c3p, tmp);
    MUL2(tmp, s4p, ss);  MUL2(w6, cc, tmp);
    MUL2(tmp, s4p, s3p); MUL2(w7, C, tmp);
    MUL2(w8, s4p, s4p);

    // T_k = A_k cos(m f0) + B_k sin(m f0)
#define TTERM(T, k, Cm, Sm) do { \
        u64 _t; \
        MUL2(_t, Bp[k], Sm); \
        FMA2(T, Ap[k], Cm, _t); } while (0)

    u64 T1, T6, T10, T13, T2, T7, T11, T3, T8, T4;
    TTERM(T1, 1, C1, S1);
    TTERM(T6, 6, C1, S1);
    TTERM(T10, 10, C1, S1);
    TTERM(T13, 13, C1, S1);
    TTERM(T2, 2, c2, s2);
    TTERM(T7, 7, c2, s2);
    TTERM(T11, 11, c2, s2);
    TTERM(T3, 3, c3, s3);
    TTERM(T8, 8, c3, s3);
    TTERM(T4, 4, c4, s4);
#undef TTERM

    // Group by power p
    u64 G2, G3, G4, G5, G6;
    ADD2(G2, Ap[5], T2);
    ADD2(G3, T6, T3);
    ADD2(G4, Ap[9], T7); ADD2(G4, G4, T4);
    ADD2(G5, T10, T8);
    ADD2(G6, Ap[12], T11);

    u64 t0, t1, t2, t3, t4, Z;
    MUL2(tmp, w1, T1);  FMA2(t0, w0, Ap[0], tmp);
    MUL2(tmp, w3, G3);  FMA2(t1, w2, G2, tmp);
    MUL2(tmp, w5, G5);  FMA2(t2, w4, G4, tmp);
    MUL2(tmp, w7, T13); FMA2(t3, w6, G6, tmp);
    MUL2(t4, w8, Ap[14]);
    ADD2(t0, t0, t1);
    ADD2(t2, t2, t3);
    ADD2(t0, t0, t2);
    ADD2(Z, t0, t4);
    return Z;
}

// ---------------------------------------------------------------------------
// Eval kernel: 4 batch elements per thread = 2 packed f32x2 chains.
// ---------------------------------------------------------------------------
__global__ __launch_bounds__(128) void eval_kernel(
    const float4* __restrict__ in, const float* __restrict__ scp,
    const float* __restrict__ bip, float4* __restrict__ out) {

    // Broadcast coefficients into packed registers ONCE.
    u64 Ap[15], Bp[15];
#pragma unroll
    for (int k = 0; k < 15; k++) {
        float a = __ldg(&g_cA[k]);
        float b = __ldg(&g_cB[k]);
        PK2(Ap[k], a, a);
        PK2(Bp[k], b, b);
    }
    const float scale = __ldg(scp);
    const float bias  = __ldg(bip);
    const float K = 0.011180339887f;  // sqrt(2/1000)/4

    u64 M1, Kp, SCp, BIp;
    PK2(M1, -1.0f, -1.0f);
    PK2(Kp, K, K);
    PK2(SCp, scale, scale);
    PK2(BIp, bias, bias);

    int t = blockIdx.x * blockDim.x + threadIdx.x;
    float4 v0 = in[2 * t];
    float4 v1 = in[2 * t + 1];

    // scalar trig (MUFU)
    float s_0, c_0, s1_0, c1_0, s_1, c_1, s1_1, c1_1;
    float s_2, c_2, s1_2, c1_2, s_3, c_3, s1_3, c1_3;
    __sincosf(0.5f * v0.y, &s_0, &c_0);
    __sincosf(v0.x, &s1_0, &c1_0);
    __sincosf(0.5f * v0.w, &s_1, &c_1);
    __sincosf(v0.z, &s1_1, &c1_1);
    __sincosf(0.5f * v1.y, &s_2, &c_2);
    __sincosf(v1.x, &s1_2, &c1_2);
    __sincosf(0.5f * v1.w, &s_3, &c_3);
    __sincosf(v1.z, &s1_3, &c1_3);

    u64 Z01 = eval_pair(c1_0, s1_0, c_0, s_0, c1_1, s1_1, c_1, s_1, Ap, Bp, M1);
    u64 Z23 = eval_pair(c1_2, s1_2, c_2, s_2, c1_3, s1_3, c_3, s_3, Ap, Bp, M1);

    // packed epilogue: r = scale * (Z + K*(Z^2 - 1)) + bias
    u64 tA, tB;
    FMA2(tA, Z01, Z01, M1);
    FMA2(tA, Kp, tA, Z01);
    FMA2(tA, SCp, tA, BIp);
    FMA2(tB, Z23, Z23, M1);
    FMA2(tB, Kp, tB, Z23);
    FMA2(tB, SCp, tB, BIp);

    float4 r;
    UPK2(r.x, r.y, tA);
    UPK2(r.z, r.w, tB);
    out[t] = r;
}

// ---------------------------------------------------------------------------
extern "C" void kernel_launch(void* const* d_in, const int* in_sizes, int n_in,
                              void* d_out, int out_size) {
    const float* inputs = (const float*)d_in[0];  // [B,2] float32
    const float* wU     = (const float*)d_in[1];  // [6]
    const float* wR     = (const float*)d_in[2];  // [6,4,3]
    const float* sc     = (const float*)d_in[3];  // [] out_scale
    const float* bi     = (const float*)d_in[4];  // [] out_bias

    setup_kernel<<<1, 192>>>(wU, wR);

    int nthreads = out_size / 4;  // 4 elements per thread
    int blocks = (nthreads + 127) / 128;
    eval_kernel<<<blocks, 128>>>((const float4*)inputs, sc, bi,
                                 (float4*)d_out);
}